// round 5
// baseline (speedup 1.0000x reference)
#include <cuda_runtime.h>
#include <cuda_bf16.h>
#include <math.h>
#include <stdint.h>

#define DT 0.01f
#define N_STEPS 20
#define PMIN (-8.0f)
#define TAB_N 512
#define TAB_STEP (16.0f / (float)TAB_N)
#define TAB_INV_STEP ((float)TAB_N / 16.0f)

// ---------------- precomputed globals (one small prep kernel) ----------------
// B operand fragments (m16n8k16 layout), bf16 hi/lo split, frag-linear:
// idx = ((kt*8+nt)*32+lane)*2+reg
__device__ __align__(16) uint32_t g_Bhi[4096];
__device__ __align__(16) uint32_t g_Blo[4096];
// scene_w transposed & f32-pair-packed: g_WsTp[j*8+dd] = pack(swT[j][2dd], swT[j][2dd+1])
__device__ __align__(16) unsigned long long g_WsTp[64 * 8];

// ---------------- helpers ----------------
typedef unsigned long long u64t;
__device__ __forceinline__ u64t pack2(float lo, float hi) {
    u64t r;
    asm("mov.b64 %0, {%1, %2};" : "=l"(r) : "f"(lo), "f"(hi));
    return r;
}
__device__ __forceinline__ void unpack2(u64t v, float& lo, float& hi) {
    asm("mov.b64 {%0, %1}, %2;" : "=f"(lo), "=f"(hi) : "l"(v));
}
__device__ __forceinline__ void ffma2(u64t& d, u64t a, u64t b) {
    asm("fma.rn.f32x2 %0, %1, %2, %0;" : "+l"(d) : "l"(a), "l"(b));
}
__device__ __forceinline__ u64t mul2(u64t a, u64t b) {
    u64t r;
    asm("mul.rn.f32x2 %0, %1, %2;" : "=l"(r) : "l"(a), "l"(b));
    return r;
}

__device__ __forceinline__ void split2(float v0, float v1, uint32_t& hi, uint32_t& lo) {
    __nv_bfloat16 h0 = __float2bfloat16(v0);
    __nv_bfloat16 h1 = __float2bfloat16(v1);
    float r0 = v0 - __bfloat162float(h0);
    float r1 = v1 - __bfloat162float(h1);
    __nv_bfloat16 l0 = __float2bfloat16(r0);
    __nv_bfloat16 l1 = __float2bfloat16(r1);
    hi = ((uint32_t)__bfloat16_as_ushort(h1) << 16) | (uint32_t)__bfloat16_as_ushort(h0);
    lo = ((uint32_t)__bfloat16_as_ushort(l1) << 16) | (uint32_t)__bfloat16_as_ushort(l0);
}

__device__ __forceinline__ void mma16816(float* d, const uint32_t* a, const uint32_t* b) {
    asm("mma.sync.aligned.m16n8k16.row.col.f32.bf16.bf16.f32 "
        "{%0,%1,%2,%3}, {%4,%5,%6,%7}, {%8,%9}, {%0,%1,%2,%3};"
        : "+f"(d[0]), "+f"(d[1]), "+f"(d[2]), "+f"(d[3])
        : "r"(a[0]), "r"(a[1]), "r"(a[2]), "r"(a[3]), "r"(b[0]), "r"(b[1]));
}

// amplitude evolution: F20(sigmoid(p))
__device__ __forceinline__ float evolve(float p) {
    float a = 1.0f / (1.0f + expf(-p));
#pragma unroll
    for (int t = 0; t < N_STEPS; t++) {
        float t2 = 1.0f - a * a;
        a = fmaf(DT, a * t2, a);
    }
    return a;
}

// ---------------- single prep kernel ----------------
// B rows: k 0..63 = Wg (ro_w1[24+k][n]); 64..123 = Wqe[k-64][n] computed inline; else 0
__device__ __forceinline__ float fetchB(int k, int n, const float* qw, const float* w1) {
    if (k < 64) return w1[(24 + k) * 64 + n];
    if (k < 124) {
        int i = k - 64;
        float acc = 0.0f;
#pragma unroll 8
        for (int m = 0; m < 64; m++)
            acc = fmaf(qw[i * 64 + m], w1[(88 + m) * 64 + n], acc);
        return acc;
    }
    return 0.0f;
}

__global__ void prep_kernel(const float* __restrict__ qw,   // (60,64)
                            const float* __restrict__ w1,   // (152,64)
                            const float* __restrict__ sw)   // scene_w (16,64)
{
    int bid = blockIdx.x, tid = threadIdx.x;
    if (bid < 16) {
        int idx = bid * 256 + tid;  // 0..4095
        int reg = idx & 1;
        int lane = (idx >> 1) & 31;
        int nt = (idx >> 6) & 7;
        int kt = idx >> 9;
        int g = lane >> 2, t = lane & 3;
        int n = nt * 8 + g;
        int k0 = kt * 16 + reg * 8 + 2 * t;
        float v0 = fetchB(k0, n, qw, w1);
        float v1 = fetchB(k0 + 1, n, qw, w1);
        uint32_t hi, lo;
        split2(v0, v1, hi, lo);
        g_Bhi[idx] = hi;
        g_Blo[idx] = lo;
    } else {
        // packed scene_w transpose
        for (int t2 = tid; t2 < 512; t2 += 256) {
            int j = t2 >> 3, dd = t2 & 7;
            g_WsTp[t2] = pack2(sw[(2 * dd) * 64 + j], sw[(2 * dd + 1) * 64 + j]);
        }
    }
}

// ---------------- main kernel ----------------
// smem offsets in u32 units
#define O_BHI 0
#define O_BLO 4096
#define O_TAB 8192          // 512 float2 = 1024 u32
#define O_SC 9216
#define O_SBS 9280
#define O_W2 9344
#define O_SB2 9472
#define O_AW 9480
#define AW_PER_WARP 2176
#define SMEM_U32 (O_AW + 4 * AW_PER_WARP)
#define SMEM_BYTES (SMEM_U32 * 4)

__global__ __launch_bounds__(128, 3) void dtg_kernel(
    const float* __restrict__ scene,    // (B,8,16)
    const float* __restrict__ query,    // (B,60)
    const float* __restrict__ scene_b,  // (64,)
    const float* __restrict__ qb,       // query_b (64,)
    const float* __restrict__ b1,       // ro_b1 (64,)
    const float* __restrict__ w1,       // ro_w1 (152,64)
    const float* __restrict__ w2,       // (64,2)
    const float* __restrict__ b2,       // (2,)
    float* __restrict__ out,            // (B,2)
    int B)
{
    extern __shared__ float smem[];
    uint32_t* sm32 = (uint32_t*)smem;

    const int tid = threadIdx.x;
    const int lane = tid & 31;
    const int wid = tid >> 5;
    const int fg = lane >> 2;
    const int ft = lane & 3;

    // ---- cooperative smem fill + in-kernel prep (overlaps LDG latency) ----
    {
        float4* bdst = (float4*)(sm32 + O_BHI);
        const float4* bh = (const float4*)g_Bhi;
        const float4* bl = (const float4*)g_Blo;
        for (int i = tid; i < 1024; i += 128) {
            bdst[i] = bh[i];
            bdst[1024 + i] = bl[i];
        }
        // table built in-kernel: each entry computes both endpoints
        for (int i = tid; i < TAB_N; i += 128) {
            float p0 = PMIN + (float)i * TAB_STEP;
            float va = evolve(p0);
            float vb = evolve(p0 + TAB_STEP);
            ((float2*)(smem + O_TAB))[i] = make_float2(va, vb - va);
        }
        // fused bias c computed in-kernel
        if (tid < 64) {
            int k = tid;
            float acc = b1[k];
#pragma unroll 4
            for (int r = 0; r < 24; r++) acc += w1[r * 64 + k];  // delta/theta amps == 1
#pragma unroll 8
            for (int m = 0; m < 64; m++)
                acc = fmaf(qb[m], w1[(88 + m) * 64 + k], acc);
            smem[O_SC + k] = acc;
            smem[O_SBS + k] = scene_b[k];
        }
        if (tid < 128) smem[O_W2 + tid] = w2[tid];
        if (tid < 2) smem[O_SB2 + tid] = b2[tid];
    }
    __syncthreads();

    const float* sbs = smem + O_SBS;
    const float* sTab = smem + O_TAB;
    uint32_t* awp = sm32 + O_AW + wid * AW_PER_WARP;
    const uint32_t* sBhi = sm32 + O_BHI;
    const uint32_t* sBlo = sm32 + O_BLO;

    const int s = blockIdx.x * 128 + wid * 32 + lane;
    const int s_eff = (s < B) ? s : (B - 1);

    // ---- scene mean -> packed s2[8] ----
    u64t s2[8];
    {
        const float4* sp = (const float4*)(scene + (size_t)s_eff * 128);
        float4 a0 = sp[0], a1 = sp[1], a2 = sp[2], a3 = sp[3];
#pragma unroll
        for (int n = 1; n < 8; n++) {
            float4 v0 = sp[n * 4 + 0], v1 = sp[n * 4 + 1];
            float4 v2 = sp[n * 4 + 2], v3 = sp[n * 4 + 3];
            a0.x += v0.x; a0.y += v0.y; a0.z += v0.z; a0.w += v0.w;
            a1.x += v1.x; a1.y += v1.y; a1.z += v1.z; a1.w += v1.w;
            a2.x += v2.x; a2.y += v2.y; a2.z += v2.z; a2.w += v2.w;
            a3.x += v3.x; a3.y += v3.y; a3.z += v3.z; a3.w += v3.w;
        }
        const float q8 = 0.125f;
        s2[0] = pack2(a0.x * q8, a0.y * q8);
        s2[1] = pack2(a0.z * q8, a0.w * q8);
        s2[2] = pack2(a1.x * q8, a1.y * q8);
        s2[3] = pack2(a1.z * q8, a1.w * q8);
        s2[4] = pack2(a2.x * q8, a2.y * q8);
        s2[5] = pack2(a2.z * q8, a2.w * q8);
        s2[6] = pack2(a3.x * q8, a3.y * q8);
        s2[7] = pack2(a3.z * q8, a3.w * q8);
    }

    // ---- stage 1: QUERY activations (k-tiles 4..7) ----
    {
        float q[64];
        const float4* qg = (const float4*)(query + (size_t)s_eff * 60);
#pragma unroll
        for (int i = 0; i < 15; i++) {
            float4 v = qg[i];
            q[4 * i + 0] = v.x;
            q[4 * i + 1] = v.y;
            q[4 * i + 2] = v.z;
            q[4 * i + 3] = v.w;
        }
        q[60] = q[61] = q[62] = q[63] = 0.0f;
#pragma unroll
        for (int c = 0; c < 32; c++) {
            uint32_t hi, lo;
            split2(q[2 * c], q[2 * c + 1], hi, lo);
            awp[lane * 33 + c] = hi;
            awp[1056 + lane * 33 + c] = lo;
        }
    }
    __syncwarp();

    float d[2][8][4];
#pragma unroll
    for (int mt = 0; mt < 2; mt++)
#pragma unroll
        for (int nt = 0; nt < 8; nt++)
#pragma unroll
            for (int e = 0; e < 4; e++) d[mt][nt][e] = 0.0f;

    // ---- MMA: query half first (staged), then gamma restage + second half ----
#pragma unroll 1
    for (int half = 0; half < 2; half++) {
        if (half == 1) {
            __syncwarp();
            const ulonglong2* wstg = (const ulonglong2*)g_WsTp;
#pragma unroll 4
            for (int c = 0; c < 32; c++) {
                float ag01[2];
#pragma unroll
                for (int u = 0; u < 2; u++) {
                    int j = 2 * c + u;
                    ulonglong2 wa = __ldg(wstg + j * 4 + 0);
                    ulonglong2 wb = __ldg(wstg + j * 4 + 1);
                    u64t acc = mul2(s2[0], wa.x);
                    ffma2(acc, s2[1], wa.y);
                    ffma2(acc, s2[2], wb.x);
                    ffma2(acc, s2[3], wb.y);
                    ulonglong2 wc = __ldg(wstg + j * 4 + 2);
                    ulonglong2 wd = __ldg(wstg + j * 4 + 3);
                    ffma2(acc, s2[4], wc.x);
                    ffma2(acc, s2[5], wc.y);
                    ffma2(acc, s2[6], wd.x);
                    ffma2(acc, s2[7], wd.y);
                    float plo, phi;
                    unpack2(acc, plo, phi);
                    float p = plo + phi + sbs[j];
                    float xf = (p - PMIN) * TAB_INV_STEP;
                    int ix = __float2int_rd(xf);
                    ix = min(max(ix, 0), TAB_N - 1);
                    float fr = xf - (float)ix;
                    float2 tv = ((const float2*)sTab)[ix];
                    ag01[u] = fmaf(fr, tv.y, tv.x);
                }
                uint32_t hi, lo;
                split2(ag01[0], ag01[1], hi, lo);
                awp[lane * 33 + c] = hi;
                awp[1056 + lane * 33 + c] = lo;
            }
            __syncwarp();
        }
#pragma unroll
        for (int ktl = 0; ktl < 4; ktl++) {
            const int kt = (half == 0) ? (4 + ktl) : ktl;
            uint32_t bh[8][2], bl[8][2];
#pragma unroll
            for (int nt = 0; nt < 8; nt++) {
                uint2 vh = *(const uint2*)(sBhi + ((kt * 8 + nt) * 32 + lane) * 2);
                uint2 vl = *(const uint2*)(sBlo + ((kt * 8 + nt) * 32 + lane) * 2);
                bh[nt][0] = vh.x; bh[nt][1] = vh.y;
                bl[nt][0] = vl.x; bl[nt][1] = vl.y;
            }
            const int c0 = ktl * 8 + ft;
            uint32_t ah[2][4], al[2][4];
#pragma unroll
            for (int mt = 0; mt < 2; mt++) {
                int r0 = mt * 16 + fg;
                ah[mt][0] = awp[r0 * 33 + c0];
                ah[mt][1] = awp[(r0 + 8) * 33 + c0];
                ah[mt][2] = awp[r0 * 33 + c0 + 4];
                ah[mt][3] = awp[(r0 + 8) * 33 + c0 + 4];
                al[mt][0] = awp[1056 + r0 * 33 + c0];
                al[mt][1] = awp[1056 + (r0 + 8) * 33 + c0];
                al[mt][2] = awp[1056 + r0 * 33 + c0 + 4];
                al[mt][3] = awp[1056 + (r0 + 8) * 33 + c0 + 4];
            }
#pragma unroll
            for (int mt = 0; mt < 2; mt++)
#pragma unroll
                for (int nt = 0; nt < 8; nt++) {
                    mma16816(d[mt][nt], ah[mt], bh[nt]);
                    mma16816(d[mt][nt], ah[mt], bl[nt]);
                    mma16816(d[mt][nt], al[mt], bh[nt]);
                }
        }
    }

    // ---- stage D to smem (per-warp, stride 68) ----
    __syncwarp();
#pragma unroll
    for (int mt = 0; mt < 2; mt++)
#pragma unroll
        for (int nt = 0; nt < 8; nt++) {
            int r0 = mt * 16 + fg;
            float* p0 = (float*)(awp + r0 * 68 + nt * 8 + 2 * ft);
            float* p1 = (float*)(awp + (r0 + 8) * 68 + nt * 8 + 2 * ft);
            *(float2*)p0 = make_float2(d[mt][nt][0], d[mt][nt][1]);
            *(float2*)p1 = make_float2(d[mt][nt][2], d[mt][nt][3]);
        }
    __syncwarp();

    // ---- epilogue: h = D + c, relu, 64->2, log_softmax ----
    {
        const float* sc = smem + O_SC;
        const float2* sw2 = (const float2*)(smem + O_W2);
        float l0 = smem[O_SB2 + 0], l1 = smem[O_SB2 + 1];
        const float4* hrow = (const float4*)(awp + lane * 68);
#pragma unroll
        for (int c = 0; c < 16; c++) {
            float4 hv = hrow[c];
            float h0 = fmaxf(hv.x + sc[4 * c + 0], 0.0f);
            float h1 = fmaxf(hv.y + sc[4 * c + 1], 0.0f);
            float h2 = fmaxf(hv.z + sc[4 * c + 2], 0.0f);
            float h3 = fmaxf(hv.w + sc[4 * c + 3], 0.0f);
            float2 w0 = sw2[4 * c + 0], w1v = sw2[4 * c + 1];
            float2 w2v = sw2[4 * c + 2], w3v = sw2[4 * c + 3];
            l0 = fmaf(h0, w0.x, l0);
            l1 = fmaf(h0, w0.y, l1);
            l0 = fmaf(h1, w1v.x, l0);
            l1 = fmaf(h1, w1v.y, l1);
            l0 = fmaf(h2, w2v.x, l0);
            l1 = fmaf(h2, w2v.y, l1);
            l0 = fmaf(h3, w3v.x, l0);
            l1 = fmaf(h3, w3v.y, l1);
        }
        float mx = fmaxf(l0, l1);
        float lse = mx + log1pf(__expf(-fabsf(l0 - l1)));
        if (s < B) ((float2*)out)[s] = make_float2(l0 - lse, l1 - lse);
    }
}

extern "C" void kernel_launch(void* const* d_in, const int* in_sizes, int n_in,
                              void* d_out, int out_size) {
    const float* scene = (const float*)d_in[0];    // (B,8,16)
    const float* query = (const float*)d_in[1];    // (B,60)
    // d_in[2..7]: phases/freqs — unused (amplitude ODE is phase-free; delta/theta
    // amplitudes start at the fixed point 1.0 and stay there)
    const float* scene_w = (const float*)d_in[8];  // (16,64)
    const float* scene_b = (const float*)d_in[9];  // (64,)
    const float* query_w = (const float*)d_in[10]; // (60,64)
    const float* query_b = (const float*)d_in[11]; // (64,)
    const float* ro_w1 = (const float*)d_in[12];   // (152,64)
    const float* ro_b1 = (const float*)d_in[13];   // (64,)
    const float* ro_w2 = (const float*)d_in[14];   // (64,2)
    const float* ro_b2 = (const float*)d_in[15];   // (2,)
    float* out = (float*)d_out;

    int B = in_sizes[0] / 128;

    static bool attr_set = false;
    if (!attr_set) {
        cudaFuncSetAttribute(dtg_kernel, cudaFuncAttributeMaxDynamicSharedMemorySize,
                             SMEM_BYTES);
        attr_set = true;
    }

    prep_kernel<<<17, 256>>>(query_w, ro_w1, scene_w);
    int grid = (B + 127) / 128;
    dtg_kernel<<<grid, 128, SMEM_BYTES>>>(scene, query, scene_b, query_b, ro_b1,
                                          ro_w1, ro_w2, ro_b2, out, B);
}

// round 6
// speedup vs baseline: 1.3641x; 1.3641x over previous
#include <cuda_runtime.h>
#include <cuda_bf16.h>
#include <math.h>
#include <stdint.h>

#define DT 0.01f
#define N_STEPS 20
#define PMIN (-8.0f)
#define TAB_N 512
#define TAB_STEP (16.0f / (float)TAB_N)
#define TAB_INV_STEP ((float)TAB_N / 16.0f)

// ---------------- precomputed globals (one parallel prep kernel) ----------------
// B fragments, uint4 = {hi_reg0, hi_reg1, lo_reg0, lo_reg1}; idx = (kt*8+nt)*32+lane
__device__ __align__(16) uint4 g_Bc[2048];
// scene_w transposed & f32-pair-packed: g_WsTp[j*8+dd] = pack(swT[j][2dd], swT[j][2dd+1])
__device__ __align__(16) unsigned long long g_WsTp[64 * 8];
__device__ __align__(16) float2 g_tab[TAB_N];   // p -> F20(sigmoid(p)) {val, delta}
__device__ __align__(16) float g_c[64];         // fused bias

// ---------------- helpers ----------------
typedef unsigned long long u64t;
__device__ __forceinline__ u64t pack2(float lo, float hi) {
    u64t r;
    asm("mov.b64 %0, {%1, %2};" : "=l"(r) : "f"(lo), "f"(hi));
    return r;
}
__device__ __forceinline__ void unpack2(u64t v, float& lo, float& hi) {
    asm("mov.b64 {%0, %1}, %2;" : "=f"(lo), "=f"(hi) : "l"(v));
}
__device__ __forceinline__ void ffma2(u64t& d, u64t a, u64t b) {
    asm("fma.rn.f32x2 %0, %1, %2, %0;" : "+l"(d) : "l"(a), "l"(b));
}
__device__ __forceinline__ u64t mul2(u64t a, u64t b) {
    u64t r;
    asm("mul.rn.f32x2 %0, %1, %2;" : "=l"(r) : "l"(a), "l"(b));
    return r;
}

__device__ __forceinline__ void split2(float v0, float v1, uint32_t& hi, uint32_t& lo) {
    __nv_bfloat16 h0 = __float2bfloat16(v0);
    __nv_bfloat16 h1 = __float2bfloat16(v1);
    float r0 = v0 - __bfloat162float(h0);
    float r1 = v1 - __bfloat162float(h1);
    __nv_bfloat16 l0 = __float2bfloat16(r0);
    __nv_bfloat16 l1 = __float2bfloat16(r1);
    hi = ((uint32_t)__bfloat16_as_ushort(h1) << 16) | (uint32_t)__bfloat16_as_ushort(h0);
    lo = ((uint32_t)__bfloat16_as_ushort(l1) << 16) | (uint32_t)__bfloat16_as_ushort(l0);
}

__device__ __forceinline__ void mma16816(float* d, const uint32_t* a, uint32_t b0, uint32_t b1) {
    asm("mma.sync.aligned.m16n8k16.row.col.f32.bf16.bf16.f32 "
        "{%0,%1,%2,%3}, {%4,%5,%6,%7}, {%8,%9}, {%0,%1,%2,%3};"
        : "+f"(d[0]), "+f"(d[1]), "+f"(d[2]), "+f"(d[3])
        : "r"(a[0]), "r"(a[1]), "r"(a[2]), "r"(a[3]), "r"(b0), "r"(b1));
}

__device__ __forceinline__ float evolve(float p) {
    float a = 1.0f / (1.0f + expf(-p));
#pragma unroll
    for (int t = 0; t < N_STEPS; t++) {
        float t2 = 1.0f - a * a;
        a = fmaf(DT, a * t2, a);
    }
    return a;
}

// ---------------- single prep kernel (all tasks parallel, no dependencies) ----
// B rows: k 0..63 = Wg (ro_w1[24+k][n]); 64..123 = Wqe[k-64][n] inline; else 0
__device__ __forceinline__ float fetchB(int k, int n, const float* qw, const float* w1) {
    if (k < 64) return w1[(24 + k) * 64 + n];
    if (k < 124) {
        int i = k - 64;
        float acc = 0.0f;
#pragma unroll 8
        for (int m = 0; m < 64; m++)
            acc = fmaf(qw[i * 64 + m], w1[(88 + m) * 64 + n], acc);
        return acc;
    }
    return 0.0f;
}

__global__ void prep_kernel(const float* __restrict__ qw,   // (60,64)
                            const float* __restrict__ qb,   // (64,)
                            const float* __restrict__ w1,   // (152,64)
                            const float* __restrict__ b1,   // (64,)
                            const float* __restrict__ sw)   // scene_w (16,64)
{
    int bid = blockIdx.x, tid = threadIdx.x;
    if (bid < 8) {
        int idx = bid * 256 + tid;  // 0..2047 -> one uint4
        int lane = idx & 31;
        int nt = (idx >> 5) & 7;
        int kt = idx >> 8;
        int g = lane >> 2, t = lane & 3;
        int n = nt * 8 + g;
        int kb = kt * 16 + 2 * t;
        float v0 = fetchB(kb, n, qw, w1);
        float v1 = fetchB(kb + 1, n, qw, w1);
        float v2 = fetchB(kb + 8, n, qw, w1);
        float v3 = fetchB(kb + 9, n, qw, w1);
        uint32_t h0, l0, h1, l1;
        split2(v0, v1, h0, l0);
        split2(v2, v3, h1, l1);
        g_Bc[idx] = make_uint4(h0, h1, l0, l1);
    } else if (bid == 8) {
        for (int t2 = tid; t2 < 512; t2 += 256) {
            int j = t2 >> 3, dd = t2 & 7;
            g_WsTp[t2] = pack2(sw[(2 * dd) * 64 + j], sw[(2 * dd + 1) * 64 + j]);
        }
    } else if (bid == 9) {
        __shared__ float v[TAB_N + 1];
        for (int i = tid; i <= TAB_N; i += 256)
            v[i] = evolve(PMIN + (float)i * TAB_STEP);
        __syncthreads();
        for (int i = tid; i < TAB_N; i += 256)
            g_tab[i] = make_float2(v[i], v[i + 1] - v[i]);
    } else {
        if (tid < 64) {
            int k = tid;
            float acc = b1[k];
            for (int r = 0; r < 24; r++) acc += w1[r * 64 + k];  // delta/theta amps == 1
            for (int m = 0; m < 64; m++)
                acc = fmaf(qb[m], w1[(88 + m) * 64 + k], acc);
            g_c[k] = acc;
        }
    }
}

// ---------------- main kernel ----------------
// smem offsets in u32 units (total ~40 KB, under 48 KB default)
#define O_TAB 0          // 512 float2 = 1024 u32
#define O_SC 1024
#define O_SBS 1088
#define O_W2 1152
#define O_SB2 1280
#define O_AW 1288        // 16B-aligned (1288*4 = 5152 = 322*16)
#define AW_PER_WARP 2176
#define SMEM_U32 (O_AW + 4 * AW_PER_WARP)
#define SMEM_BYTES (SMEM_U32 * 4)

__global__ __launch_bounds__(128, 4) void dtg_kernel(
    const float* __restrict__ scene,    // (B,8,16)
    const float* __restrict__ query,    // (B,60)
    const float* __restrict__ scene_b,  // (64,)
    const float* __restrict__ w2,       // (64,2)
    const float* __restrict__ b2,       // (2,)
    float* __restrict__ out,            // (B,2)
    int B)
{
    __shared__ float smem[SMEM_U32];
    uint32_t* sm32 = (uint32_t*)smem;

    const int tid = threadIdx.x;
    const int lane = tid & 31;
    const int wid = tid >> 5;
    const int fg = lane >> 2;
    const int ft = lane & 3;

    const int s = blockIdx.x * 128 + wid * 32 + lane;
    const int s_eff = (s < B) ? s : (B - 1);

    // ---- light startup: copy precomputed tables to smem ----
    {
        const float4* tg = (const float4*)g_tab;
        float4* ts = (float4*)(smem + O_TAB);
        for (int i = tid; i < 256; i += 128) ts[i] = tg[i];
        if (tid < 64) {
            smem[O_SC + tid] = g_c[tid];
            smem[O_SBS + tid] = scene_b[tid];
        }
        if (tid < 128) smem[O_W2 + tid] = w2[tid];
        if (tid < 2) smem[O_SB2 + tid] = b2[tid];
    }
    __syncthreads();

    const float* sbs = smem + O_SBS;
    const float* sTab = smem + O_TAB;
    uint32_t* awp = sm32 + O_AW + wid * AW_PER_WARP;

    // ---- stage 1: QUERY activations (k-tiles 4..7); q dead after this block ----
    {
        float q[64];
        const float4* qg = (const float4*)(query + (size_t)s_eff * 60);
#pragma unroll
        for (int i = 0; i < 15; i++) {
            float4 v = qg[i];
            q[4 * i + 0] = v.x;
            q[4 * i + 1] = v.y;
            q[4 * i + 2] = v.z;
            q[4 * i + 3] = v.w;
        }
        q[60] = q[61] = q[62] = q[63] = 0.0f;
#pragma unroll
        for (int c = 0; c < 32; c++) {
            uint32_t hi, lo;
            split2(q[2 * c], q[2 * c + 1], hi, lo);
            awp[lane * 33 + c] = hi;
            awp[1056 + lane * 33 + c] = lo;
        }
    }
    __syncwarp();

    float d[2][8][4];
#pragma unroll
    for (int mt = 0; mt < 2; mt++)
#pragma unroll
        for (int nt = 0; nt < 8; nt++)
#pragma unroll
            for (int e = 0; e < 4; e++) d[mt][nt][e] = 0.0f;

    // ---- MMA: query half first, then gamma restage + second half ----
#pragma unroll 1
    for (int half = 0; half < 2; half++) {
        if (half == 1) {
            __syncwarp();
            // scene load + mean HERE (keeps s2 out of the live range of MMA half 0)
            u64t s2[8];
            {
                const float4* sp = (const float4*)(scene + (size_t)s_eff * 128);
                float4 a0 = sp[0], a1 = sp[1], a2 = sp[2], a3 = sp[3];
#pragma unroll
                for (int n = 1; n < 8; n++) {
                    float4 v0 = sp[n * 4 + 0], v1 = sp[n * 4 + 1];
                    float4 v2 = sp[n * 4 + 2], v3 = sp[n * 4 + 3];
                    a0.x += v0.x; a0.y += v0.y; a0.z += v0.z; a0.w += v0.w;
                    a1.x += v1.x; a1.y += v1.y; a1.z += v1.z; a1.w += v1.w;
                    a2.x += v2.x; a2.y += v2.y; a2.z += v2.z; a2.w += v2.w;
                    a3.x += v3.x; a3.y += v3.y; a3.z += v3.z; a3.w += v3.w;
                }
                const float q8 = 0.125f;
                s2[0] = pack2(a0.x * q8, a0.y * q8);
                s2[1] = pack2(a0.z * q8, a0.w * q8);
                s2[2] = pack2(a1.x * q8, a1.y * q8);
                s2[3] = pack2(a1.z * q8, a1.w * q8);
                s2[4] = pack2(a2.x * q8, a2.y * q8);
                s2[5] = pack2(a2.z * q8, a2.w * q8);
                s2[6] = pack2(a3.x * q8, a3.y * q8);
                s2[7] = pack2(a3.z * q8, a3.w * q8);
            }
            const ulonglong2* wstg = (const ulonglong2*)g_WsTp;
#pragma unroll 4
            for (int c = 0; c < 32; c++) {
                float ag01[2];
#pragma unroll
                for (int u = 0; u < 2; u++) {
                    int j = 2 * c + u;
                    ulonglong2 wa = __ldg(wstg + j * 4 + 0);
                    ulonglong2 wb = __ldg(wstg + j * 4 + 1);
                    u64t acc = mul2(s2[0], wa.x);
                    ffma2(acc, s2[1], wa.y);
                    ffma2(acc, s2[2], wb.x);
                    ffma2(acc, s2[3], wb.y);
                    ulonglong2 wc = __ldg(wstg + j * 4 + 2);
                    ulonglong2 wd = __ldg(wstg + j * 4 + 3);
                    ffma2(acc, s2[4], wc.x);
                    ffma2(acc, s2[5], wc.y);
                    ffma2(acc, s2[6], wd.x);
                    ffma2(acc, s2[7], wd.y);
                    float plo, phi;
                    unpack2(acc, plo, phi);
                    float p = plo + phi + sbs[j];
                    float xf = (p - PMIN) * TAB_INV_STEP;
                    int ix = __float2int_rd(xf);
                    ix = min(max(ix, 0), TAB_N - 1);
                    float fr = xf - (float)ix;
                    float2 tv = ((const float2*)sTab)[ix];
                    ag01[u] = fmaf(fr, tv.y, tv.x);
                }
                uint32_t hi, lo;
                split2(ag01[0], ag01[1], hi, lo);
                awp[lane * 33 + c] = hi;
                awp[1056 + lane * 33 + c] = lo;
            }
            __syncwarp();
        }
#pragma unroll
        for (int ktl = 0; ktl < 4; ktl++) {
            const int kt = (half == 0) ? (4 + ktl) : ktl;
            // B fragments from global (broadcast, L1-resident): one LDG.128 per nt
            uint4 bv[8];
#pragma unroll
            for (int nt = 0; nt < 8; nt++)
                bv[nt] = __ldg(&g_Bc[(kt * 8 + nt) * 32 + lane]);
            // A fragments from per-warp staged tile
            const int c0 = ktl * 8 + ft;
            uint32_t ah[2][4], al[2][4];
#pragma unroll
            for (int mt = 0; mt < 2; mt++) {
                int r0 = mt * 16 + fg;
                ah[mt][0] = awp[r0 * 33 + c0];
                ah[mt][1] = awp[(r0 + 8) * 33 + c0];
                ah[mt][2] = awp[r0 * 33 + c0 + 4];
                ah[mt][3] = awp[(r0 + 8) * 33 + c0 + 4];
                al[mt][0] = awp[1056 + r0 * 33 + c0];
                al[mt][1] = awp[1056 + (r0 + 8) * 33 + c0];
                al[mt][2] = awp[1056 + r0 * 33 + c0 + 4];
                al[mt][3] = awp[1056 + (r0 + 8) * 33 + c0 + 4];
            }
#pragma unroll
            for (int mt = 0; mt < 2; mt++)
#pragma unroll
                for (int nt = 0; nt < 8; nt++) {
                    mma16816(d[mt][nt], ah[mt], bv[nt].x, bv[nt].y);
                    mma16816(d[mt][nt], ah[mt], bv[nt].z, bv[nt].w);
                    mma16816(d[mt][nt], al[mt], bv[nt].x, bv[nt].y);
                }
        }
    }

    // ---- stage D to smem (per-warp, stride 68) ----
    __syncwarp();
#pragma unroll
    for (int mt = 0; mt < 2; mt++)
#pragma unroll
        for (int nt = 0; nt < 8; nt++) {
            int r0 = mt * 16 + fg;
            float* p0 = (float*)(awp + r0 * 68 + nt * 8 + 2 * ft);
            float* p1 = (float*)(awp + (r0 + 8) * 68 + nt * 8 + 2 * ft);
            *(float2*)p0 = make_float2(d[mt][nt][0], d[mt][nt][1]);
            *(float2*)p1 = make_float2(d[mt][nt][2], d[mt][nt][3]);
        }
    __syncwarp();

    // ---- epilogue: h = D + c, relu, 64->2, log_softmax ----
    {
        const float* sc = smem + O_SC;
        const float2* sw2 = (const float2*)(smem + O_W2);
        float l0 = smem[O_SB2 + 0], l1 = smem[O_SB2 + 1];
        const float4* hrow = (const float4*)(awp + lane * 68);
#pragma unroll
        for (int c = 0; c < 16; c++) {
            float4 hv = hrow[c];
            float h0 = fmaxf(hv.x + sc[4 * c + 0], 0.0f);
            float h1 = fmaxf(hv.y + sc[4 * c + 1], 0.0f);
            float h2 = fmaxf(hv.z + sc[4 * c + 2], 0.0f);
            float h3 = fmaxf(hv.w + sc[4 * c + 3], 0.0f);
            float2 w0 = sw2[4 * c + 0], w1v = sw2[4 * c + 1];
            float2 w2v = sw2[4 * c + 2], w3v = sw2[4 * c + 3];
            l0 = fmaf(h0, w0.x, l0);
            l1 = fmaf(h0, w0.y, l1);
            l0 = fmaf(h1, w1v.x, l0);
            l1 = fmaf(h1, w1v.y, l1);
            l0 = fmaf(h2, w2v.x, l0);
            l1 = fmaf(h2, w2v.y, l1);
            l0 = fmaf(h3, w3v.x, l0);
            l1 = fmaf(h3, w3v.y, l1);
        }
        float mx = fmaxf(l0, l1);
        float lse = mx + log1pf(__expf(-fabsf(l0 - l1)));
        if (s < B) ((float2*)out)[s] = make_float2(l0 - lse, l1 - lse);
    }
}

extern "C" void kernel_launch(void* const* d_in, const int* in_sizes, int n_in,
                              void* d_out, int out_size) {
    const float* scene = (const float*)d_in[0];    // (B,8,16)
    const float* query = (const float*)d_in[1];    // (B,60)
    // d_in[2..7]: phases/freqs — unused (amplitude ODE is phase-free; delta/theta
    // amplitudes start at the fixed point 1.0 and stay there)
    const float* scene_w = (const float*)d_in[8];  // (16,64)
    const float* scene_b = (const float*)d_in[9];  // (64,)
    const float* query_w = (const float*)d_in[10]; // (60,64)
    const float* query_b = (const float*)d_in[11]; // (64,)
    const float* ro_w1 = (const float*)d_in[12];   // (152,64)
    const float* ro_b1 = (const float*)d_in[13];   // (64,)
    const float* ro_w2 = (const float*)d_in[14];   // (64,2)
    const float* ro_b2 = (const float*)d_in[15];   // (2,)
    float* out = (float*)d_out;

    int B = in_sizes[0] / 128;

    prep_kernel<<<11, 256>>>(query_w, query_b, ro_w1, ro_b1, scene_w);
    int grid = (B + 127) / 128;
    dtg_kernel<<<grid, 128>>>(scene, query, scene_b, ro_w2, ro_b2, out, B);
}

// round 7
// speedup vs baseline: 1.4301x; 1.0484x over previous
#include <cuda_runtime.h>
#include <cuda_bf16.h>
#include <math.h>
#include <stdint.h>

#define DT 0.01f
#define N_STEPS 20
#define PMIN (-8.0f)
#define TAB_N 512
#define TAB_STEP (16.0f / (float)TAB_N)
#define TAB_INV_STEP ((float)TAB_N / 16.0f)

// ---------------- precomputed globals (one parallel prep kernel) ----------------
// B fragments, uint4 = {hi_reg0, hi_reg1, lo_reg0, lo_reg1}; idx = (kt*8+nt)*32+lane
__device__ __align__(16) uint4 g_Bc[2048];
// scene_w transposed & f32-pair-packed: g_WsTp[j*8+dd] = pack(swT[j][2dd], swT[j][2dd+1])
__device__ __align__(16) unsigned long long g_WsTp[64 * 8];
__device__ __align__(16) float2 g_tab[TAB_N];   // p -> F20(sigmoid(p)) {val, delta}
__device__ __align__(16) float g_c[64];         // fused bias

// ---------------- helpers ----------------
typedef unsigned long long u64t;
__device__ __forceinline__ u64t pack2(float lo, float hi) {
    u64t r;
    asm("mov.b64 %0, {%1, %2};" : "=l"(r) : "f"(lo), "f"(hi));
    return r;
}
__device__ __forceinline__ void unpack2(u64t v, float& lo, float& hi) {
    asm("mov.b64 {%0, %1}, %2;" : "=f"(lo), "=f"(hi) : "l"(v));
}
__device__ __forceinline__ void ffma2(u64t& d, u64t a, u64t b) {
    asm("fma.rn.f32x2 %0, %1, %2, %0;" : "+l"(d) : "l"(a), "l"(b));
}
__device__ __forceinline__ u64t mul2(u64t a, u64t b) {
    u64t r;
    asm("mul.rn.f32x2 %0, %1, %2;" : "=l"(r) : "l"(a), "l"(b));
    return r;
}
__device__ __forceinline__ uint32_t smem_u32(const void* p) {
    uint32_t a;
    asm("{ .reg .u64 t; cvta.to.shared.u64 t, %1; cvt.u32.u64 %0, t; }"
        : "=r"(a) : "l"(p));
    return a;
}

__device__ __forceinline__ void split2(float v0, float v1, uint32_t& hi, uint32_t& lo) {
    __nv_bfloat16 h0 = __float2bfloat16(v0);
    __nv_bfloat16 h1 = __float2bfloat16(v1);
    float r0 = v0 - __bfloat162float(h0);
    float r1 = v1 - __bfloat162float(h1);
    __nv_bfloat16 l0 = __float2bfloat16(r0);
    __nv_bfloat16 l1 = __float2bfloat16(r1);
    hi = ((uint32_t)__bfloat16_as_ushort(h1) << 16) | (uint32_t)__bfloat16_as_ushort(h0);
    lo = ((uint32_t)__bfloat16_as_ushort(l1) << 16) | (uint32_t)__bfloat16_as_ushort(l0);
}

__device__ __forceinline__ void mma16816(float* d, const uint32_t* a, uint32_t b0, uint32_t b1) {
    asm("mma.sync.aligned.m16n8k16.row.col.f32.bf16.bf16.f32 "
        "{%0,%1,%2,%3}, {%4,%5,%6,%7}, {%8,%9}, {%0,%1,%2,%3};"
        : "+f"(d[0]), "+f"(d[1]), "+f"(d[2]), "+f"(d[3])
        : "r"(a[0]), "r"(a[1]), "r"(a[2]), "r"(a[3]), "r"(b0), "r"(b1));
}

__device__ __forceinline__ void ldmx4(uint32_t* r, uint32_t saddr) {
    asm volatile("ldmatrix.sync.aligned.m8n8.x4.shared.b16 {%0,%1,%2,%3}, [%4];"
                 : "=r"(r[0]), "=r"(r[1]), "=r"(r[2]), "=r"(r[3]) : "r"(saddr));
}

__device__ __forceinline__ float evolve(float p) {
    float a = 1.0f / (1.0f + expf(-p));
#pragma unroll
    for (int t = 0; t < N_STEPS; t++) {
        float t2 = 1.0f - a * a;
        a = fmaf(DT, a * t2, a);
    }
    return a;
}

// ---------------- single prep kernel (all tasks parallel) ----------------
__device__ __forceinline__ float fetchB(int k, int n, const float* qw, const float* w1) {
    if (k < 64) return w1[(24 + k) * 64 + n];
    if (k < 124) {
        int i = k - 64;
        float acc = 0.0f;
#pragma unroll 8
        for (int m = 0; m < 64; m++)
            acc = fmaf(qw[i * 64 + m], w1[(88 + m) * 64 + n], acc);
        return acc;
    }
    return 0.0f;
}

__global__ void prep_kernel(const float* __restrict__ qw,   // (60,64)
                            const float* __restrict__ qb,   // (64,)
                            const float* __restrict__ w1,   // (152,64)
                            const float* __restrict__ b1,   // (64,)
                            const float* __restrict__ sw)   // scene_w (16,64)
{
    int bid = blockIdx.x, tid = threadIdx.x;
    if (bid < 8) {
        int idx = bid * 256 + tid;  // one uint4 each
        int lane = idx & 31;
        int nt = (idx >> 5) & 7;
        int kt = idx >> 8;
        int g = lane >> 2, t = lane & 3;
        int n = nt * 8 + g;
        int kb = kt * 16 + 2 * t;
        float v0 = fetchB(kb, n, qw, w1);
        float v1 = fetchB(kb + 1, n, qw, w1);
        float v2 = fetchB(kb + 8, n, qw, w1);
        float v3 = fetchB(kb + 9, n, qw, w1);
        uint32_t h0, l0, h1, l1;
        split2(v0, v1, h0, l0);
        split2(v2, v3, h1, l1);
        g_Bc[idx] = make_uint4(h0, h1, l0, l1);
    } else if (bid == 8) {
        for (int t2 = tid; t2 < 512; t2 += 256) {
            int j = t2 >> 3, dd = t2 & 7;
            g_WsTp[t2] = pack2(sw[(2 * dd) * 64 + j], sw[(2 * dd + 1) * 64 + j]);
        }
    } else if (bid == 9) {
        __shared__ float v[TAB_N + 1];
        for (int i = tid; i <= TAB_N; i += 256)
            v[i] = evolve(PMIN + (float)i * TAB_STEP);
        __syncthreads();
        for (int i = tid; i < TAB_N; i += 256)
            g_tab[i] = make_float2(v[i], v[i + 1] - v[i]);
    } else {
        if (tid < 64) {
            int k = tid;
            float acc = b1[k];
            for (int r = 0; r < 24; r++) acc += w1[r * 64 + k];  // delta/theta amps == 1
            for (int m = 0; m < 64; m++)
                acc = fmaf(qb[m], w1[(88 + m) * 64 + k], acc);
            g_c[k] = acc;
        }
    }
}

// ---------------- main kernel ----------------
// smem offsets in u32 units
#define O_TAB 0          // 512 float2 = 1024 u32
#define O_SC 1024
#define O_SBS 1088
#define O_W2 1152
#define O_SB2 1280
#define O_AW 1288        // 16B-aligned
// per-warp region: A-staging hi [0,1024) + lo [1024,2048), D-staging overlays [0,2176)
#define AW_PER_WARP 2176
#define SMEM_U32 (O_AW + 4 * AW_PER_WARP)

__global__ __launch_bounds__(128, 4) void dtg_kernel(
    const float* __restrict__ scene,    // (B,8,16)
    const float* __restrict__ query,    // (B,60)
    const float* __restrict__ scene_b,  // (64,)
    const float* __restrict__ w2,       // (64,2)
    const float* __restrict__ b2,       // (2,)
    float* __restrict__ out,            // (B,2)
    int B)
{
    __shared__ float smem[SMEM_U32];
    uint32_t* sm32 = (uint32_t*)smem;

    const int tid = threadIdx.x;
    const int lane = tid & 31;
    const int wid = tid >> 5;
    const int lane7 = lane & 7;

    const int s = blockIdx.x * 128 + wid * 32 + lane;
    const int s_eff = (s < B) ? s : (B - 1);

    // ---- light startup: copy precomputed tables to smem ----
    {
        const float4* tg = (const float4*)g_tab;
        float4* ts = (float4*)(smem + O_TAB);
        for (int i = tid; i < 256; i += 128) ts[i] = tg[i];
        if (tid < 64) {
            smem[O_SC + tid] = g_c[tid];
            smem[O_SBS + tid] = scene_b[tid];
        }
        if (tid < 128) smem[O_W2 + tid] = w2[tid];
        if (tid < 2) smem[O_SB2 + tid] = b2[tid];
    }
    __syncthreads();

    const float* sbs = smem + O_SBS;
    const float* sTab = smem + O_TAB;
    uint32_t* awp = sm32 + O_AW + wid * AW_PER_WARP;
    const uint32_t aw_sh = smem_u32(awp);

    // ---- stage 1: QUERY activations (k-tiles 4..7), swizzled STS.128 ----
    {
        float q[64];
        const float4* qg = (const float4*)(query + (size_t)s_eff * 60);
#pragma unroll
        for (int i = 0; i < 15; i++) {
            float4 v = qg[i];
            q[4 * i + 0] = v.x;
            q[4 * i + 1] = v.y;
            q[4 * i + 2] = v.z;
            q[4 * i + 3] = v.w;
        }
        q[60] = q[61] = q[62] = q[63] = 0.0f;
#pragma unroll
        for (int cc = 0; cc < 8; cc++) {
            uint32_t hv[4], lv[4];
#pragma unroll
            for (int u = 0; u < 4; u++)
                split2(q[8 * cc + 2 * u], q[8 * cc + 2 * u + 1], hv[u], lv[u]);
            int phys = cc ^ lane7;
            *(uint4*)(awp + lane * 32 + phys * 4) = make_uint4(hv[0], hv[1], hv[2], hv[3]);
            *(uint4*)(awp + 1024 + lane * 32 + phys * 4) = make_uint4(lv[0], lv[1], lv[2], lv[3]);
        }
    }
    __syncwarp();

    float d[2][8][4];
#pragma unroll
    for (int mt = 0; mt < 2; mt++)
#pragma unroll
        for (int nt = 0; nt < 8; nt++)
#pragma unroll
            for (int e = 0; e < 4; e++) d[mt][nt][e] = 0.0f;

    // ldmatrix per-thread address pieces: rows = mt*16 + (lane&15); k-chunk half = lane>>4
    const int lrow = lane & 15;
    const int lkg = (lane >> 4) & 1;
    const uint32_t ldm_base = aw_sh + (uint32_t)lrow * 128u;  // row*32 u32 *4B

    // ---- MMA: query half first, then gamma restage + second half ----
#pragma unroll 1
    for (int half = 0; half < 2; half++) {
        if (half == 1) {
            __syncwarp();
            // scene load + mean HERE (keeps s2 out of live range of MMA half 0)
            u64t s2[8];
            {
                const float4* sp = (const float4*)(scene + (size_t)s_eff * 128);
                float4 a0 = sp[0], a1 = sp[1], a2 = sp[2], a3 = sp[3];
#pragma unroll
                for (int n = 1; n < 8; n++) {
                    float4 v0 = sp[n * 4 + 0], v1 = sp[n * 4 + 1];
                    float4 v2 = sp[n * 4 + 2], v3 = sp[n * 4 + 3];
                    a0.x += v0.x; a0.y += v0.y; a0.z += v0.z; a0.w += v0.w;
                    a1.x += v1.x; a1.y += v1.y; a1.z += v1.z; a1.w += v1.w;
                    a2.x += v2.x; a2.y += v2.y; a2.z += v2.z; a2.w += v2.w;
                    a3.x += v3.x; a3.y += v3.y; a3.z += v3.z; a3.w += v3.w;
                }
                const float q8 = 0.125f;
                s2[0] = pack2(a0.x * q8, a0.y * q8);
                s2[1] = pack2(a0.z * q8, a0.w * q8);
                s2[2] = pack2(a1.x * q8, a1.y * q8);
                s2[3] = pack2(a1.z * q8, a1.w * q8);
                s2[4] = pack2(a2.x * q8, a2.y * q8);
                s2[5] = pack2(a2.z * q8, a2.w * q8);
                s2[6] = pack2(a3.x * q8, a3.y * q8);
                s2[7] = pack2(a3.z * q8, a3.w * q8);
            }
            const ulonglong2* wstg = (const ulonglong2*)g_WsTp;
#pragma unroll 2
            for (int cc = 0; cc < 8; cc++) {
                uint32_t hv[4], lv[4];
#pragma unroll
                for (int u = 0; u < 4; u++) {
                    float ag01[2];
#pragma unroll
                    for (int v = 0; v < 2; v++) {
                        int j = 8 * cc + 2 * u + v;
                        ulonglong2 wa = __ldg(wstg + j * 4 + 0);
                        ulonglong2 wb = __ldg(wstg + j * 4 + 1);
                        u64t acc = mul2(s2[0], wa.x);
                        ffma2(acc, s2[1], wa.y);
                        ffma2(acc, s2[2], wb.x);
                        ffma2(acc, s2[3], wb.y);
                        ulonglong2 wc = __ldg(wstg + j * 4 + 2);
                        ulonglong2 wd = __ldg(wstg + j * 4 + 3);
                        ffma2(acc, s2[4], wc.x);
                        ffma2(acc, s2[5], wc.y);
                        ffma2(acc, s2[6], wd.x);
                        ffma2(acc, s2[7], wd.y);
                        float plo, phi;
                        unpack2(acc, plo, phi);
                        float p = plo + phi + sbs[j];
                        float xf = (p - PMIN) * TAB_INV_STEP;
                        int ix = __float2int_rd(xf);
                        ix = min(max(ix, 0), TAB_N - 1);
                        float fr = xf - (float)ix;
                        float2 tv = ((const float2*)sTab)[ix];
                        ag01[v] = fmaf(fr, tv.y, tv.x);
                    }
                    split2(ag01[0], ag01[1], hv[u], lv[u]);
                }
                int phys = cc ^ lane7;
                *(uint4*)(awp + lane * 32 + phys * 4) = make_uint4(hv[0], hv[1], hv[2], hv[3]);
                *(uint4*)(awp + 1024 + lane * 32 + phys * 4) = make_uint4(lv[0], lv[1], lv[2], lv[3]);
            }
            __syncwarp();
        }
#pragma unroll
        for (int ktl = 0; ktl < 4; ktl++) {
            const int kt = (half == 0) ? (4 + ktl) : ktl;
            // B fragments from global (L1-resident): one LDG.128 per nt
            uint4 bv[8];
#pragma unroll
            for (int nt = 0; nt < 8; nt++)
                bv[nt] = __ldg(&g_Bc[(kt * 8 + nt) * 32 + lane]);
            // A fragments via ldmatrix.x4 (swizzled)
            const int chunk = ktl * 2 + lkg;
            const uint32_t coff = (uint32_t)((chunk ^ lane7) * 16);
            uint32_t ah[2][4], al[2][4];
            ldmx4(ah[0], ldm_base + coff);
            ldmx4(ah[1], ldm_base + 2048u + coff);
            ldmx4(al[0], ldm_base + 4096u + coff);
            ldmx4(al[1], ldm_base + 6144u + coff);
#pragma unroll
            for (int mt = 0; mt < 2; mt++)
#pragma unroll
                for (int nt = 0; nt < 8; nt++) {
                    mma16816(d[mt][nt], ah[mt], bv[nt].x, bv[nt].y);
                    mma16816(d[mt][nt], ah[mt], bv[nt].z, bv[nt].w);
                    mma16816(d[mt][nt], al[mt], bv[nt].x, bv[nt].y);
                }
        }
    }

    // ---- stage D to smem (per-warp, stride 68) ----
    const int fg = lane >> 2;
    const int ft = lane & 3;
    __syncwarp();
#pragma unroll
    for (int mt = 0; mt < 2; mt++)
#pragma unroll
        for (int nt = 0; nt < 8; nt++) {
            int r0 = mt * 16 + fg;
            float* p0 = (float*)(awp + r0 * 68 + nt * 8 + 2 * ft);
            float* p1 = (float*)(awp + (r0 + 8) * 68 + nt * 8 + 2 * ft);
            *(float2*)p0 = make_float2(d[mt][nt][0], d[mt][nt][1]);
            *(float2*)p1 = make_float2(d[mt][nt][2], d[mt][nt][3]);
        }
    __syncwarp();

    // ---- epilogue: h = D + c, relu, 64->2, log_softmax ----
    {
        const float* sc = smem + O_SC;
        const float2* sw2 = (const float2*)(smem + O_W2);
        float l0 = smem[O_SB2 + 0], l1 = smem[O_SB2 + 1];
        const float4* hrow = (const float4*)(awp + lane * 68);
#pragma unroll
        for (int c = 0; c < 16; c++) {
            float4 hv = hrow[c];
            float h0 = fmaxf(hv.x + sc[4 * c + 0], 0.0f);
            float h1 = fmaxf(hv.y + sc[4 * c + 1], 0.0f);
            float h2 = fmaxf(hv.z + sc[4 * c + 2], 0.0f);
            float h3 = fmaxf(hv.w + sc[4 * c + 3], 0.0f);
            float2 w0 = sw2[4 * c + 0], w1v = sw2[4 * c + 1];
            float2 w2v = sw2[4 * c + 2], w3v = sw2[4 * c + 3];
            l0 = fmaf(h0, w0.x, l0);
            l1 = fmaf(h0, w0.y, l1);
            l0 = fmaf(h1, w1v.x, l0);
            l1 = fmaf(h1, w1v.y, l1);
            l0 = fmaf(h2, w2v.x, l0);
            l1 = fmaf(h2, w2v.y, l1);
            l0 = fmaf(h3, w3v.x, l0);
            l1 = fmaf(h3, w3v.y, l1);
        }
        float mx = fmaxf(l0, l1);
        float lse = mx + log1pf(__expf(-fabsf(l0 - l1)));
        if (s < B) ((float2*)out)[s] = make_float2(l0 - lse, l1 - lse);
    }
}

extern "C" void kernel_launch(void* const* d_in, const int* in_sizes, int n_in,
                              void* d_out, int out_size) {
    const float* scene = (const float*)d_in[0];    // (B,8,16)
    const float* query = (const float*)d_in[1];    // (B,60)
    // d_in[2..7]: phases/freqs — unused (amplitude ODE is phase-free; delta/theta
    // amplitudes start at the fixed point 1.0 and stay there)
    const float* scene_w = (const float*)d_in[8];  // (16,64)
    const float* scene_b = (const float*)d_in[9];  // (64,)
    const float* query_w = (const float*)d_in[10]; // (60,64)
    const float* query_b = (const float*)d_in[11]; // (64,)
    const float* ro_w1 = (const float*)d_in[12];   // (152,64)
    const float* ro_b1 = (const float*)d_in[13];   // (64,)
    const float* ro_w2 = (const float*)d_in[14];   // (64,2)
    const float* ro_b2 = (const float*)d_in[15];   // (2,)
    float* out = (float*)d_out;

    int B = in_sizes[0] / 128;

    prep_kernel<<<11, 256>>>(query_w, query_b, ro_w1, ro_b1, scene_w);
    int grid = (B + 127) / 128;
    dtg_kernel<<<grid, 128>>>(scene, query, scene_b, ro_w2, ro_b2, out, B);
}